// round 9
// baseline (speedup 1.0000x reference)
#include <cuda_runtime.h>

#define BSZ  2048
#define SEQL 50
#define NP   (BSZ*SEQL)      /* 102400 pairs */
#define ATTD 64
#define HIDD 128
#define G4   512             /* 4*HID gates */

typedef unsigned long long ull;

/* ---------------- device scratch (no cudaMalloc allowed) ---------------- */
__device__ float  g_ctx[(size_t)NP * ATTD];        /* [s][b][64]  26 MB  */
__device__ float  g_xg [(size_t)NP * G4];          /* [s][b][512] 210 MB */
__device__ float4 g_whh4t[(HIDD/4) * G4];          /* [kq][col] packed W_hh^T */

/* ---------------- f32x2 helpers (2 MACs / instr on sm_103a) ------------- */
__device__ __forceinline__ void fma2(ull& d, ull a, ull b){
    asm("fma.rn.f32x2 %0, %1, %2, %0;" : "+l"(d) : "l"(a), "l"(b));
}
__device__ __forceinline__ float2 unpk(ull v){
    float2 r; asm("mov.b64 {%0, %1}, %2;" : "=f"(r.x), "=f"(r.y) : "l"(v)); return r;
}
__device__ __forceinline__ float hsum2(ull v){ float2 f = unpk(v); return f.x + f.y; }
__device__ __forceinline__ ull pack2(float x){
    ull r; asm("mov.b64 %0, {%1, %1};" : "=l"(r) : "f"(x)); return r;
}
__device__ __forceinline__ float sigm(float x){ return 1.f/(1.f + __expf(-x)); }
__device__ __forceinline__ float tanhfast(float x){ return 1.f - 2.f/(__expf(2.f*x) + 1.f); }

/* ============ kernel 0: transpose+pack W_hh -> [kq][col] float4 ========= */
__global__ void k_pack(const float* __restrict__ Whh){
    int t = threadIdx.x, kq = blockIdx.x;             /* <<<32,512>>> */
    g_whh4t[kq*G4 + t] = make_float4(Whh[t*HIDD + 4*kq],   Whh[t*HIDD + 4*kq+1],
                                     Whh[t*HIDD + 4*kq+2], Whh[t*HIDD + 4*kq+3]);
}

/* ============ kernel 1: edge attention via algebraic folding (R8) ======= */
__global__ void __launch_bounds__(128) k_ctx(
    const float* __restrict__ seqs, const float* __restrict__ ets, const int* __restrict__ masks,
    const float* __restrict__ Wfus, const float* __restrict__ bfus,
    const float* __restrict__ Wk,   const float* __restrict__ bk,
    const float* __restrict__ Wq,   const float* __restrict__ bq,
    const float* __restrict__ Wv,   const float* __restrict__ bv)
{
    __shared__ __align__(16) float  s_fus[20*64];   /* [k][o]; row19 = bfus */
    __shared__ __align__(16) float2 s_fT[32*20];    /* [pair][k] Wfus rows  */
    __shared__ __align__(16) float2 s_wq2[64*32];   /* [o][pair]            */
    __shared__ __align__(16) float2 s_wv2[32*64];   /* [pair][o]            */
    __shared__ __align__(16) float  s_wk[6*64];     /* [k][o]               */
    __shared__ float s_bq[64], s_bv[64], s_bk[64];
    __shared__ __align__(16) float  s_raw[2][96];
    __shared__ __align__(16) float2 s_u[2][4*32];   /* [g][h*32+pair]       */
    __shared__ __align__(16) float2 s_e[2][4*32];
    __shared__ int s_msk[2][12];

    const int tid = threadIdx.x;
    for (int i = tid; i < 20*64; i += 128){
        int k = i >> 6, o = i & 63;
        s_fus[i] = (k < 19) ? Wfus[o*19 + k] : bfus[o];
    }
    for (int i = tid; i < 32*20; i += 128){
        int p = i / 20, k = i % 20;
        float a0 = (k < 19) ? Wfus[(2*p)*19 + k]   : bfus[2*p];
        float a1 = (k < 19) ? Wfus[(2*p+1)*19 + k] : bfus[2*p+1];
        s_fT[i] = make_float2(a0, a1);
    }
    for (int i = tid; i < 64*32; i += 128){
        int o = i >> 5, p = i & 31;
        s_wq2[i] = make_float2(Wq[o*64 + 2*p], Wq[o*64 + 2*p + 1]);
    }
    for (int i = tid; i < 32*64; i += 128){
        int p = i >> 6, o = i & 63;
        s_wv2[i] = make_float2(Wv[o*64 + 2*p], Wv[o*64 + 2*p + 1]);
    }
    for (int i = tid; i < 6*64; i += 128){ int k = i >> 6, o = i & 63; s_wk[i] = Wk[o*6 + k]; }
    if (tid < 64){ s_bq[tid] = bq[tid]; s_bv[tid] = bv[tid]; s_bk[tid] = bk[tid]; }
    __syncthreads();

    const int g   = tid >> 6;
    const int o   = tid & 63;
    const int h   = o >> 4;                 /* head 0..3 */
    const int cl  = o & 15;                 /* lane within head segment */
    const int hb  = o & 16;                 /* warp-local segment base */
    const int bar = g + 1;
    const int ggid    = blockIdx.x*2 + g;
    const int ngroups = gridDim.x*2;
    const unsigned FULL = 0xffffffffu;

    for (int pr = ggid; pr < NP; pr += ngroups){
        const float* sq = seqs + (size_t)pr*54;
        const float* se = ets  + (size_t)pr*36;
        for (int i = o; i < 90; i += 64) s_raw[g][i] = (i < 54) ? sq[i] : se[i-54];
        if (o < 9) s_msk[g][o] = masks[(size_t)pr*9 + o];
        asm volatile("bar.sync %0, 64;" :: "r"(bar) : "memory");
        const float* rg = s_raw[g];

        /* key[o] from self cell (n=4), beta = sum_d key*bq over segment */
        float keyo = s_bk[o];
        #pragma unroll
        for (int k = 0; k < 6; k++) keyo += s_wk[k*64 + o] * rg[24 + k];
        float beta = keyo * s_bq[o];
        #pragma unroll
        for (int mm = 8; mm >= 1; mm >>= 1) beta += __shfl_xor_sync(FULL, beta, mm);

        /* u_h[c] = sum_d key[h,d] Wq[h16+d, c]  (2 c-pairs per lane) */
        ull u0 = 0ULL, u1 = 0ULL;
        #pragma unroll
        for (int d = 0; d < 16; d++){
            float kd = __shfl_sync(FULL, keyo, hb | d);
            ull kd2 = pack2(kd);
            fma2(u0, kd2, *reinterpret_cast<const ull*>(&s_wq2[(h*16 + d)*32 + cl]));
            fma2(u1, kd2, *reinterpret_cast<const ull*>(&s_wq2[(h*16 + d)*32 + cl + 16]));
        }
        s_u[g][h*32 + cl]      = unpk(u0);
        s_u[g][h*32 + cl + 16] = unpk(u1);
        __syncwarp();

        /* wtil[k] = sum_c u[c] Wfus[c,k]; lane cl covers k=cl and k=16+(cl&3) */
        int k2 = 16 + (cl & 3);
        ull t1 = 0ULL, t2 = 0ULL;
        #pragma unroll 8
        for (int p = 0; p < 32; p++){
            ull up = *reinterpret_cast<const ull*>(&s_u[g][h*32 + p]);
            fma2(t1, up, *reinterpret_cast<const ull*>(&s_fT[p*20 + cl]));
            fma2(t2, up, *reinterpret_cast<const ull*>(&s_fT[p*20 + k2]));
        }
        float wt1 = hsum2(t1), wt2 = hsum2(t2);
        float gamma = __shfl_sync(FULL, wt2, hb | 3);       /* k=19: u.bfus */

        float wk_[10];
        #pragma unroll
        for (int k = 0; k < 10; k++) wk_[k] = __shfl_sync(FULL, wt1, hb | k);
        int k10 = 10 + cl;                                  /* valid cl<9 */
        float sA = __shfl_sync(FULL, wt1, hb | (k10 & 15));
        float sB = __shfl_sync(FULL, wt2, hb | ((k10 - 16) & 3));
        float wsel = (k10 < 16) ? sA : sB;

        /* att for slot n=cl (<9): x_n . wtil + gamma + beta, scale, mask */
        float att;
        {
            int n = (cl < 9) ? cl : 8;
            float t = gamma + beta + wsel;
            #pragma unroll
            for (int k = 0; k < 6; k++) t += rg[n*6 + k] * wk_[k];
            #pragma unroll
            for (int j = 0; j < 4; j++) t += rg[54 + n*4 + j] * wk_[6 + j];
            t *= 0.25f;
            att = (cl < 9) ? ((s_msk[g][n] == 0) ? -1e10f : t) : -1e30f;
        }
        /* softmax over 9 inside 16-lane segment */
        float m = att;
        #pragma unroll
        for (int mm = 8; mm >= 1; mm >>= 1) m = fmaxf(m, __shfl_xor_sync(FULL, m, mm));
        float ex = __expf(att - m);
        float ssum = ex;
        #pragma unroll
        for (int mm = 8; mm >= 1; mm >>= 1) ssum += __shfl_xor_sync(FULL, ssum, mm);
        float inv = 1.f / ssum;
        float a[9];
        #pragma unroll
        for (int n = 0; n < 9; n++) a[n] = __shfl_sync(FULL, ex, hb | n) * inv;

        /* xbar[k] = sum_n a[n] x_n[k], k=0..9 (lane k computes, then gather) */
        float xb = 0.f;
        {
            int kx = (cl < 10) ? cl : 9;
            #pragma unroll
            for (int n = 0; n < 9; n++)
                xb += a[n] * ((kx < 6) ? rg[n*6 + kx] : rg[54 + n*4 + (kx - 6)]);
        }
        float xk[10];
        #pragma unroll
        for (int k = 0; k < 10; k++) xk[k] = __shfl_sync(FULL, xb, hb | k);

        /* ebar pairs: Wfus xbar + sum_n a_n Wfus[:,10+n] + bfus */
        ull e0 = 0ULL, e1 = 0ULL;
        #pragma unroll
        for (int k = 0; k < 10; k++){
            ull xk2 = pack2(xk[k]);
            fma2(e0, xk2, *reinterpret_cast<const ull*>(&s_fus[k*64 + 2*cl]));
            fma2(e1, xk2, *reinterpret_cast<const ull*>(&s_fus[k*64 + 2*cl + 32]));
        }
        #pragma unroll
        for (int n = 0; n < 9; n++){
            ull an2 = pack2(a[n]);
            fma2(e0, an2, *reinterpret_cast<const ull*>(&s_fus[(10+n)*64 + 2*cl]));
            fma2(e1, an2, *reinterpret_cast<const ull*>(&s_fus[(10+n)*64 + 2*cl + 32]));
        }
        {
            float2 f0 = unpk(e0), f1 = unpk(e1);
            const float2 b0 = *reinterpret_cast<const float2*>(&s_fus[19*64 + 2*cl]);
            const float2 b1 = *reinterpret_cast<const float2*>(&s_fus[19*64 + 2*cl + 32]);
            s_e[g][h*32 + cl]      = make_float2(f0.x + b0.x, f0.y + b0.y);
            s_e[g][h*32 + cl + 16] = make_float2(f1.x + b1.x, f1.y + b1.y);
        }
        __syncwarp();

        /* ctx[o] = Wv[o,:] . ebar_h + bv[o] */
        ull cacc = 0ULL;
        #pragma unroll 8
        for (int p = 0; p < 32; p++){
            ull ep = *reinterpret_cast<const ull*>(&s_e[g][h*32 + p]);
            fma2(cacc, ep, *reinterpret_cast<const ull*>(&s_wv2[p*64 + o]));
        }
        float ctx = hsum2(cacc) + s_bv[o];

        int b = pr / SEQL, s = pr - b*SEQL;            /* time-major for LSTM */
        g_ctx[((size_t)s*BSZ + b)*ATTD + o] = ctx;
        asm volatile("bar.sync %0, 64;" :: "r"(bar) : "memory");
    }
}

/* ============ kernel 2: xg = ctx @ W_ih^T + (b_ih + b_hh) (R8) ========== */
__global__ void __launch_bounds__(128) k_xg(
    const float* __restrict__ Wih, const float* __restrict__ bih, const float* __restrict__ bhh)
{
    __shared__ __align__(16) float4 s_w4[16*128];  /* [kq][jj] 4-k packed, 32KB */
    __shared__ float s_b[128];
    __shared__ __align__(16) float s_c[16*64];     /* 16 ctx rows */
    const int tid = threadIdx.x;
    const int jt  = blockIdx.x & 3;
    const int rb  = blockIdx.x >> 2;               /* 0..221 */
    const int j   = jt*128 + tid;

    for (int i = tid; i < 16*128; i += 128){
        int kq = i >> 7, jj = i & 127, jg = jt*128 + jj;
        s_w4[i] = make_float4(Wih[jg*64 + 4*kq],   Wih[jg*64 + 4*kq+1],
                              Wih[jg*64 + 4*kq+2], Wih[jg*64 + 4*kq+3]);
    }
    s_b[tid] = bih[j] + bhh[j];
    __syncthreads();

    for (int r0 = rb*16; r0 < NP; r0 += 222*16){   /* NP % 16 == 0 */
        for (int i = tid; i < 16*64; i += 128) s_c[i] = g_ctx[(size_t)r0*64 + i];
        __syncthreads();
        ull acc2[16];
        #pragma unroll
        for (int r = 0; r < 16; r++) acc2[r] = 0ULL;
        #pragma unroll 4
        for (int kq = 0; kq < 16; kq++){
            ulonglong2 w = *reinterpret_cast<const ulonglong2*>(&s_w4[kq*128 + tid]);
            #pragma unroll
            for (int r = 0; r < 16; r++){
                ulonglong2 c = *reinterpret_cast<const ulonglong2*>(&s_c[r*64 + 4*kq]);
                fma2(acc2[r], w.x, c.x);
                fma2(acc2[r], w.y, c.y);
            }
        }
        float bj = s_b[tid];
        #pragma unroll
        for (int r = 0; r < 16; r++){
            g_xg[(size_t)(r0+r)*G4 + j] = hsum2(acc2[r]) + bj;
        }
        __syncthreads();
    }
}

/* ============ kernel 3: recurrent LSTM scan + output GEMM ================
 * 256 blocks x 256 threads (2/SM), block owns 8 batch rows.
 * Thread = 8 rows x 2 gate-cols {c, c+256} (16 f32x2 accumulators):
 * per kq 2 coalesced LDG.128 + 8 broadcast LDS.128 + 32 fma2.
 * Weight L1 traffic halved vs 4-row tile (each weight reused 8 rows).     */
__global__ void __launch_bounds__(256) k_lstm(
    const float* __restrict__ Wout, const float* __restrict__ bout, float* __restrict__ outp)
{
    __shared__ __align__(16) float s_h[8*HIDD];    /* 4 KB  */
    __shared__ __align__(16) float s_g[64*HIDD];   /* 32 KB: gates 8*G4=4096,
                                                      epilogue W_out^T 8192 */
    const int tid = threadIdx.x;
    const int c   = tid;                           /* owns cols c and c+256 */
    const int b0  = blockIdx.x * 8;
    for (int i = tid; i < 8*HIDD; i += 256) s_h[i] = 0.f;
    float creg[4] = {0.f, 0.f, 0.f, 0.f};
    __syncthreads();

    const ulonglong2* __restrict__ wp = reinterpret_cast<const ulonglong2*>(g_whh4t);

    for (int s = 0; s < SEQL; s++){
        /* prefetch xg gate biases for own 16 outputs (hide L2 latency) */
        const float* xgp = g_xg + ((size_t)s*BSZ + b0)*G4;
        float xv0[8], xv1[8];
        #pragma unroll
        for (int r = 0; r < 8; r++){
            xv0[r] = __ldg(&xgp[(size_t)r*G4 + c]);
            xv1[r] = __ldg(&xgp[(size_t)r*G4 + c + 256]);
        }

        ull acc0[8], acc1[8];
        #pragma unroll
        for (int r = 0; r < 8; r++){ acc0[r] = 0ULL; acc1[r] = 0ULL; }

        #pragma unroll 4
        for (int kq = 0; kq < 32; kq++){
            ulonglong2 w0 = __ldg(&wp[kq*G4 + c]);          /* LDG.128 coalesced */
            ulonglong2 w1 = __ldg(&wp[kq*G4 + 256 + c]);
            ulonglong2 h[8];
            #pragma unroll
            for (int r = 0; r < 8; r++)
                h[r] = *reinterpret_cast<const ulonglong2*>(&s_h[r*HIDD + 4*kq]);
            #pragma unroll
            for (int r = 0; r < 8; r++){
                fma2(acc0[r], w0.x, h[r].x);
                fma2(acc0[r], w0.y, h[r].y);
                fma2(acc1[r], w1.x, h[r].x);
                fma2(acc1[r], w1.y, h[r].y);
            }
        }

        #pragma unroll
        for (int r = 0; r < 8; r++){
            s_g[r*G4 + c]       = hsum2(acc0[r]) + xv0[r];
            s_g[r*G4 + c + 256] = hsum2(acc1[r]) + xv1[r];
        }
        __syncthreads();
        #pragma unroll
        for (int q = 0; q < 4; q++){                        /* 1024 cells / 256 thr */
            int cell = q*256 + tid;
            int r = cell >> 7, j = cell & 127;
            float ig = sigm(s_g[r*G4 + j]);
            float fg = sigm(s_g[r*G4 + 128 + j]);
            float gg = tanhfast(s_g[r*G4 + 256 + j]);
            float og = sigm(s_g[r*G4 + 384 + j]);
            float cc = fg*creg[q] + ig*gg;
            creg[q]  = cc;
            s_h[r*HIDD + j] = og * tanhfast(cc);
        }
        __syncthreads();
    }

    /* out = h_last @ W_out^T + b_out ; stage W_out^T [jj][oo] in s_g */
    float* s_wo = s_g;
    for (int i = tid; i < 64*HIDD; i += 256){
        int oo = i & 63, jj = i >> 6;
        s_wo[jj*64 + oo] = Wout[oo*HIDD + jj];
    }
    __syncthreads();
    #pragma unroll
    for (int q = 0; q < 2; q++){                            /* 512 outputs */
        int idx = q*256 + tid;
        int r = idx >> 6, oo = idx & 63;
        float acc = __ldg(&bout[oo]);
        #pragma unroll 8
        for (int jj = 0; jj < HIDD; jj++) acc += s_wo[jj*64 + oo] * s_h[r*HIDD + jj];
        outp[(size_t)(b0 + r)*64 + oo] = acc;
    }
}

/* ======================================================================== */
extern "C" void kernel_launch(void* const* d_in, const int* in_sizes, int n_in,
                              void* d_out, int out_size)
{
    const float* seqs = (const float*)d_in[0];
    const float* ets  = (const float*)d_in[1];
    const int*   msk  = (const int*)  d_in[2];
    const float* Wfus = (const float*)d_in[3];
    const float* bfus = (const float*)d_in[4];
    const float* Wk   = (const float*)d_in[5];
    const float* bk   = (const float*)d_in[6];
    const float* Wq   = (const float*)d_in[7];
    const float* bq   = (const float*)d_in[8];
    const float* Wv   = (const float*)d_in[9];
    const float* bv   = (const float*)d_in[10];
    const float* Wih  = (const float*)d_in[11];
    const float* Whh  = (const float*)d_in[12];
    const float* bih  = (const float*)d_in[13];
    const float* bhh  = (const float*)d_in[14];
    const float* Wout = (const float*)d_in[15];
    const float* bout = (const float*)d_in[16];
    float* outp = (float*)d_out;

    k_pack<<<32, 512>>>(Whh);
    k_ctx <<<592, 128>>>(seqs, ets, msk, Wfus, bfus, Wk, bk, Wq, bq, Wv, bv);
    k_xg  <<<888, 128>>>(Wih, bih, bhh);
    k_lstm<<<256, 256>>>(Wout, bout, outp);
}

// round 10
// speedup vs baseline: 1.2375x; 1.2375x over previous
#include <cuda_runtime.h>

#define BSZ  2048
#define SEQL 50
#define NP   (BSZ*SEQL)      /* 102400 pairs */
#define ATTD 64
#define HIDD 128
#define G4   512             /* 4*HID gates */

typedef unsigned long long ull;

/* ---------------- device scratch (no cudaMalloc allowed) ---------------- */
__device__ float  g_ctx[(size_t)NP * ATTD];        /* [s][b][64]  26 MB  */
__device__ float  g_xg [(size_t)NP * G4];          /* [s][b][512] 210 MB */
__device__ float4 g_whh4t[(HIDD/4) * G4];          /* [kq][col] packed W_hh^T */
__device__ float  g_M[4*7*20];                     /* bilinear att matrices */
__device__ float  g_G[20*64];                      /* folded Wv*Ffus (+bv)  */

/* ---------------- f32x2 helpers ----------------------------------------- */
__device__ __forceinline__ void fma2(ull& d, ull a, ull b){
    asm("fma.rn.f32x2 %0, %1, %2, %0;" : "+l"(d) : "l"(a), "l"(b));
}
__device__ __forceinline__ float2 unpk(ull v){
    float2 r; asm("mov.b64 {%0, %1}, %2;" : "=f"(r.x), "=f"(r.y) : "l"(v)); return r;
}
__device__ __forceinline__ float hsum2(ull v){ float2 f = unpk(v); return f.x + f.y; }
__device__ __forceinline__ float sigm(float x){ return 1.f/(1.f + __expf(-x)); }
__device__ __forceinline__ float tanhfast(float x){ return 1.f - 2.f/(__expf(2.f*x) + 1.f); }

/* ============ kernel P: fold weights into M (4x7x20) and G (20x64) ======
 * M_h = 0.25 * [Wk_h|bk_h]^T ( Wq_h [Wfus|bfus] + bq_h e19^T )  (7x20)
 * G[k][o] = sum_c Wv[o][c]*F[c][k];  G[19][o] += bv[o]
 * blocks 0-3: head h (Qtilde in smem, then M). blocks 4-23: G for k=bid-4. */
__global__ void k_prep(
    const float* __restrict__ Wfus, const float* __restrict__ bfus,
    const float* __restrict__ Wk,   const float* __restrict__ bk,
    const float* __restrict__ Wq,   const float* __restrict__ bq,
    const float* __restrict__ Wv,   const float* __restrict__ bv)
{
    __shared__ float sQ[16*20];
    const int bid = blockIdx.x, tid = threadIdx.x;      /* <<<24,128>>> */
    if (bid < 4){
        int h = bid;
        for (int i = tid; i < 320; i += 128){
            int k = i % 20, d = i / 20, od = h*16 + d;
            float acc = (k == 19) ? bq[od] : 0.f;
            for (int c = 0; c < 64; c++){
                float f = (k < 19) ? Wfus[c*19 + k] : bfus[c];
                acc += Wq[od*64 + c] * f;
            }
            sQ[i] = acc;
        }
        __syncthreads();
        for (int i = tid; i < 140; i += 128){
            int k = i % 20, dp = i / 20;
            float acc = 0.f;
            for (int d = 0; d < 16; d++){
                int o = h*16 + d;
                float wk = (dp < 6) ? Wk[o*6 + dp] : bk[o];
                acc += wk * sQ[d*20 + k];
            }
            g_M[h*140 + dp*20 + k] = 0.25f * acc;
        }
    } else {
        int k = bid - 4;                                /* 0..19 */
        for (int o = tid; o < 64; o += 128){
            float acc = (k == 19) ? bv[o] : 0.f;
            for (int c = 0; c < 64; c++){
                float f = (k < 19) ? Wfus[c*19 + k] : bfus[c];
                acc += Wv[o*64 + c] * f;
            }
            g_G[k*64 + o] = acc;
        }
    }
}

/* ============ kernel 0: transpose+pack W_hh -> [kq][col] float4 ========= */
__global__ void k_pack(const float* __restrict__ Whh){
    int t = threadIdx.x, kq = blockIdx.x;             /* <<<32,512>>> */
    g_whh4t[kq*G4 + t] = make_float4(Whh[t*HIDD + 4*kq],   Whh[t*HIDD + 4*kq+1],
                                     Whh[t*HIDD + 4*kq+2], Whh[t*HIDD + 4*kq+3]);
}

/* ============ kernel 1: attention via precomputed bilinear form =========
 * att[n,h] = xs~^T M_h xn~ ; ctx[o] = sum_k G[k][o] xbar~[k].
 * 64 threads/pair = 4 heads x 16 lanes; ~3.3K MAC/pair.                   */
__global__ void __launch_bounds__(128) k_ctx(
    const float* __restrict__ seqs, const float* __restrict__ ets,
    const int* __restrict__ masks)
{
    __shared__ __align__(16) float sM[560];
    __shared__ __align__(16) float sG[20*64];
    __shared__ __align__(16) float s_raw[2][96];
    __shared__ float s_t[2][4][20];
    __shared__ int s_msk[2][12];

    const int tid = threadIdx.x;
    for (int i = tid; i < 560;   i += 128) sM[i] = g_M[i];
    for (int i = tid; i < 20*64; i += 128) sG[i] = g_G[i];
    __syncthreads();

    const int g   = tid >> 6;
    const int o   = tid & 63;
    const int h   = o >> 4;
    const int cl  = o & 15;
    const int hb  = o & 16;                /* segment base within warp */
    const int bar = g + 1;
    const int ggid    = blockIdx.x*2 + g;
    const int ngroups = gridDim.x*2;
    const unsigned FULL = 0xffffffffu;
    const float* Mh = &sM[h*140];

    for (int pr = ggid; pr < NP; pr += ngroups){
        const float* sq = seqs + (size_t)pr*54;
        const float* se = ets  + (size_t)pr*36;
        for (int i = o; i < 90; i += 64) s_raw[g][i] = (i < 54) ? sq[i] : se[i-54];
        if (o < 9) s_msk[g][o] = masks[(size_t)pr*9 + o];
        asm volatile("bar.sync %0, 64;" :: "r"(bar) : "memory");
        const float* rg = s_raw[g];

        float xs[6];
        #pragma unroll
        for (int d = 0; d < 6; d++) xs[d] = rg[24 + d];

        /* t_h[k] = xs~^T M_h : lane cl covers k=cl (and k=16+cl for cl<4) */
        {
            float t1 = Mh[6*20 + cl];
            #pragma unroll
            for (int d = 0; d < 6; d++) t1 += xs[d] * Mh[d*20 + cl];
            s_t[g][h][cl] = t1;
            if (cl < 4){
                int k2 = 16 + cl;
                float t2 = Mh[6*20 + k2];
                #pragma unroll
                for (int d = 0; d < 6; d++) t2 += xs[d] * Mh[d*20 + k2];
                s_t[g][h][k2] = t2;
            }
        }
        __syncwarp();

        /* att for slot n=cl (<9): t.xn~ (one-hot -> direct t[10+n]) */
        float att;
        {
            int n = (cl < 9) ? cl : 8;
            const float* tp = s_t[g][h];
            float v = tp[19] + tp[10 + n];
            #pragma unroll
            for (int k = 0; k < 6; k++) v += tp[k] * rg[n*6 + k];
            #pragma unroll
            for (int j = 0; j < 4; j++) v += tp[6 + j] * rg[54 + n*4 + j];
            att = (cl < 9) ? ((s_msk[g][n] == 0) ? -1e10f : v) : -1e30f;
        }

        /* softmax over 9 inside 16-lane segment */
        float m = att;
        #pragma unroll
        for (int mm = 8; mm >= 1; mm >>= 1) m = fmaxf(m, __shfl_xor_sync(FULL, m, mm));
        float ex = __expf(att - m);
        float ssum = ex;
        #pragma unroll
        for (int mm = 8; mm >= 1; mm >>= 1) ssum += __shfl_xor_sync(FULL, ssum, mm);
        float inv = 1.f / ssum;
        float a[9];
        #pragma unroll
        for (int n = 0; n < 9; n++) a[n] = __shfl_sync(FULL, ex, hb | n) * inv;

        /* xbar[k<10] = sum_n a[n] xn[k]; lane kx=cl computes, then gather */
        float xb = 0.f;
        {
            int kx = (cl < 10) ? cl : 9;
            #pragma unroll
            for (int n = 0; n < 9; n++)
                xb += a[n] * ((kx < 6) ? rg[n*6 + kx] : rg[54 + n*4 + (kx - 6)]);
        }
        float xk[10];
        #pragma unroll
        for (int k = 0; k < 10; k++) xk[k] = __shfl_sync(FULL, xb, hb | k);

        /* ctx[o] = G[19][o] + sum_{k<10} xk G[k][o] + sum_n a_n G[10+n][o] */
        float c = sG[19*64 + o];
        #pragma unroll
        for (int k = 0; k < 10; k++) c += xk[k] * sG[k*64 + o];
        #pragma unroll
        for (int n = 0; n < 9; n++) c += a[n] * sG[(10+n)*64 + o];

        int b = pr / SEQL, s = pr - b*SEQL;            /* time-major for LSTM */
        g_ctx[((size_t)s*BSZ + b)*ATTD + o] = c;
        asm volatile("bar.sync %0, 64;" :: "r"(bar) : "memory");
    }
}

/* ============ kernel 2: xg = ctx @ W_ih^T + (b_ih + b_hh) (proven) ====== */
__global__ void __launch_bounds__(128) k_xg(
    const float* __restrict__ Wih, const float* __restrict__ bih, const float* __restrict__ bhh)
{
    __shared__ __align__(16) float4 s_w4[16*128];  /* [kq][jj] 4-k packed, 32KB */
    __shared__ float s_b[128];
    __shared__ __align__(16) float s_c[16*64];     /* 16 ctx rows */
    const int tid = threadIdx.x;
    const int jt  = blockIdx.x & 3;
    const int rb  = blockIdx.x >> 2;               /* 0..221 */
    const int j   = jt*128 + tid;

    for (int i = tid; i < 16*128; i += 128){
        int kq = i >> 7, jj = i & 127, jg = jt*128 + jj;
        s_w4[i] = make_float4(Wih[jg*64 + 4*kq],   Wih[jg*64 + 4*kq+1],
                              Wih[jg*64 + 4*kq+2], Wih[jg*64 + 4*kq+3]);
    }
    s_b[tid] = bih[j] + bhh[j];
    __syncthreads();

    for (int r0 = rb*16; r0 < NP; r0 += 222*16){   /* NP % 16 == 0 */
        for (int i = tid; i < 16*64; i += 128) s_c[i] = g_ctx[(size_t)r0*64 + i];
        __syncthreads();
        ull acc2[16];
        #pragma unroll
        for (int r = 0; r < 16; r++) acc2[r] = 0ULL;
        #pragma unroll 4
        for (int kq = 0; kq < 16; kq++){
            ulonglong2 w = *reinterpret_cast<const ulonglong2*>(&s_w4[kq*128 + tid]);
            #pragma unroll
            for (int r = 0; r < 16; r++){
                ulonglong2 c = *reinterpret_cast<const ulonglong2*>(&s_c[r*64 + 4*kq]);
                fma2(acc2[r], w.x, c.x);
                fma2(acc2[r], w.y, c.y);
            }
        }
        float bj = s_b[tid];
        #pragma unroll
        for (int r = 0; r < 16; r++){
            g_xg[(size_t)(r0+r)*G4 + j] = hsum2(acc2[r]) + bj;
        }
        __syncthreads();
    }
}

/* ============ kernel 3: recurrent LSTM scan + output GEMM (R7 best) ===== */
__global__ void __launch_bounds__(512, 2) k_lstm(
    const float* __restrict__ Wout, const float* __restrict__ bout, float* __restrict__ outp)
{
    __shared__ __align__(16) float s_h[8*HIDD];    /* 4 KB  */
    __shared__ __align__(16) float s_g[64*HIDD];   /* 32 KB */
    const int tid = threadIdx.x;
    const int c   = tid & 255;                     /* owns cols c and c+256 */
    const int rh  = tid >> 8;                      /* rows 4rh..4rh+3 */
    const int b0  = blockIdx.x * 8;
    for (int i = tid; i < 8*HIDD; i += 512) s_h[i] = 0.f;
    float creg[2] = {0.f, 0.f};
    __syncthreads();

    const ulonglong2* __restrict__ wp = reinterpret_cast<const ulonglong2*>(g_whh4t);

    for (int s = 0; s < SEQL; s++){
        const float* xgp = g_xg + ((size_t)s*BSZ + b0)*G4;
        float xv0[4], xv1[4];
        #pragma unroll
        for (int r = 0; r < 4; r++){
            int row = rh*4 + r;
            xv0[r] = __ldg(&xgp[(size_t)row*G4 + c]);
            xv1[r] = __ldg(&xgp[(size_t)row*G4 + c + 256]);
        }

        ull acc0[4], acc1[4];
        #pragma unroll
        for (int r = 0; r < 4; r++){ acc0[r] = 0ULL; acc1[r] = 0ULL; }

        #pragma unroll 4
        for (int kq = 0; kq < 32; kq++){
            ulonglong2 w0 = __ldg(&wp[kq*G4 + c]);
            ulonglong2 w1 = __ldg(&wp[kq*G4 + 256 + c]);
            ulonglong2 h[4];
            #pragma unroll
            for (int r = 0; r < 4; r++)
                h[r] = *reinterpret_cast<const ulonglong2*>(&s_h[(rh*4 + r)*HIDD + 4*kq]);
            #pragma unroll
            for (int r = 0; r < 4; r++){
                fma2(acc0[r], w0.x, h[r].x);
                fma2(acc0[r], w0.y, h[r].y);
                fma2(acc1[r], w1.x, h[r].x);
                fma2(acc1[r], w1.y, h[r].y);
            }
        }

        #pragma unroll
        for (int r = 0; r < 4; r++){
            int row = rh*4 + r;
            s_g[row*G4 + c]       = hsum2(acc0[r]) + xv0[r];
            s_g[row*G4 + c + 256] = hsum2(acc1[r]) + xv1[r];
        }
        __syncthreads();
        #pragma unroll
        for (int q = 0; q < 2; q++){                        /* 1024 cells / 512 thr */
            int cell = q*512 + tid;
            int r = cell >> 7, j = cell & 127;
            float ig = sigm(s_g[r*G4 + j]);
            float fg = sigm(s_g[r*G4 + 128 + j]);
            float gg = tanhfast(s_g[r*G4 + 256 + j]);
            float og = sigm(s_g[r*G4 + 384 + j]);
            float cc = fg*creg[q] + ig*gg;
            creg[q]  = cc;
            s_h[r*HIDD + j] = og * tanhfast(cc);
        }
        __syncthreads();
    }

    /* out = h_last @ W_out^T + b_out */
    float* s_wo = s_g;
    for (int i = tid; i < 64*HIDD; i += 512){
        int oo = i & 63, jj = i >> 6;
        s_wo[jj*64 + oo] = Wout[oo*HIDD + jj];
    }
    __syncthreads();
    {
        int r = tid >> 6, oo = tid & 63;
        float acc = __ldg(&bout[oo]);
        #pragma unroll 8
        for (int jj = 0; jj < HIDD; jj++) acc += s_wo[jj*64 + oo] * s_h[r*HIDD + jj];
        outp[(size_t)(b0 + r)*64 + oo] = acc;
    }
}

/* ======================================================================== */
extern "C" void kernel_launch(void* const* d_in, const int* in_sizes, int n_in,
                              void* d_out, int out_size)
{
    const float* seqs = (const float*)d_in[0];
    const float* ets  = (const float*)d_in[1];
    const int*   msk  = (const int*)  d_in[2];
    const float* Wfus = (const float*)d_in[3];
    const float* bfus = (const float*)d_in[4];
    const float* Wk   = (const float*)d_in[5];
    const float* bk   = (const float*)d_in[6];
    const float* Wq   = (const float*)d_in[7];
    const float* bq   = (const float*)d_in[8];
    const float* Wv   = (const float*)d_in[9];
    const float* bv   = (const float*)d_in[10];
    const float* Wih  = (const float*)d_in[11];
    const float* Whh  = (const float*)d_in[12];
    const float* bih  = (const float*)d_in[13];
    const float* bhh  = (const float*)d_in[14];
    const float* Wout = (const float*)d_in[15];
    const float* bout = (const float*)d_in[16];
    float* outp = (float*)d_out;

    k_prep<<<24, 128>>>(Wfus, bfus, Wk, bk, Wq, bq, Wv, bv);
    k_pack<<<32, 512>>>(Whh);
    k_ctx <<<592, 128>>>(seqs, ets, msk);
    k_xg  <<<888, 128>>>(Wih, bih, bhh);
    k_lstm<<<256, 512>>>(Wout, bout, outp);
}